// round 4
// baseline (speedup 1.0000x reference)
#include <cuda_runtime.h>
#include <math.h>

#define NN 20000
#define NE 2000
#define DD 64
#define NS 3
#define EPAD 2048

#define NSPLIT 50
#define RPS 400          // rows per split (NN / NSPLIT)
#define TK 40            // k-chunk for big matmuls (RPS % TK == 0, NE % TK == 0)
#define TN 32            // node-rows per block in pass_n

// ---------------- scratch (static device globals; no allocation) ----------------
__device__ float g_x[NN*DD];       // fe @ W2
__device__ float g_y[EPAD*DD];     // edge @ W3
__device__ float g_node[NN*DD];    // pre-BN node
__device__ float g_acc[EPAD*DD];   // pass1 split-K accumulator
__device__ float g_acc2[EPAD*DD];  // pass3 split-K accumulator
__device__ float g_csum[EPAD];     // column exp-sums

// ---------------- zero scratch (grid 512x256 == EPAD*DD exactly) ----------------
__global__ void zero_scratch_kernel() {
    int i = blockIdx.x * blockDim.x + threadIdx.x;
    g_acc[i]  = 0.f;
    g_acc2[i] = 0.f;
    if (i < EPAD) g_csum[i] = 0.f;
}

// ---------------- x = fe @ W2   [N,64]x[64,64] ----------------
__global__ __launch_bounds__(256) void gemm_x_kernel(const float* __restrict__ Fe,
                                                     const float* __restrict__ W2) {
    __shared__ __align__(16) float Fs[64][64];
    __shared__ __align__(16) float Ws[64][64];
    const int t  = threadIdx.x;
    const int n0 = blockIdx.x * 64;
    const int tx = t & 15, ty = t >> 4;
#pragma unroll
    for (int i = 0; i < 16; i++) {
        int idx = t + 256 * i;
        int r = idx >> 6, c = idx & 63;
        int n = n0 + r;
        Fs[r][c] = (n < NN) ? Fe[(size_t)n * DD + c] : 0.f;
        Ws[r][c] = W2[idx];
    }
    __syncthreads();
    float a[4][4];
#pragma unroll
    for (int i = 0; i < 4; i++)
#pragma unroll
        for (int j = 0; j < 4; j++) a[i][j] = 0.f;
#pragma unroll
    for (int k = 0; k < 64; k++) {
        float fv[4];
#pragma unroll
        for (int i = 0; i < 4; i++) fv[i] = Fs[ty * 4 + i][k];
        float4 w4 = *(const float4*)&Ws[k][tx * 4];
        float wv[4] = {w4.x, w4.y, w4.z, w4.w};
#pragma unroll
        for (int i = 0; i < 4; i++)
#pragma unroll
            for (int j = 0; j < 4; j++) a[i][j] = fmaf(fv[i], wv[j], a[i][j]);
    }
#pragma unroll
    for (int i = 0; i < 4; i++) {
        int n = n0 + ty * 4 + i;
        if (n < NN) {
#pragma unroll
            for (int j = 0; j < 4; j++) g_x[(size_t)n * DD + tx * 4 + j] = a[i][j];
        }
    }
}

// ---------------- pass 1 / pass 3: acc[e,d] += sum_n exp(A[n,e]) * X[n,d] --------
// PASS==1: X=g_x, acc=g_acc, also accumulates column exp-sums into g_csum.
// PASS==3: X=g_node, acc=g_acc2.
template <int PASS>
__global__ __launch_bounds__(256) void pass_et_kernel(const float* __restrict__ A) {
    const float* __restrict__ X = (PASS == 1) ? g_x : g_node;
    float* acc = (PASS == 1) ? g_acc : g_acc2;
    __shared__ __align__(16) float Ps[TK][64];
    __shared__ __align__(16) float Xs[TK][64];
    __shared__ float cred[256];
    const int t      = threadIdx.x;
    const int e_base = blockIdx.x * 64;
    const int row0   = blockIdx.y * RPS;
    const int tx = t & 15, ty = t >> 4;
    const int e_loc  = t & 63;                 // fixed per thread (256 % 64 == 0)
    const bool e_ok  = (e_base + e_loc) < NE;
    float cs = 0.f;
    float a[4][4];
#pragma unroll
    for (int i = 0; i < 4; i++)
#pragma unroll
        for (int j = 0; j < 4; j++) a[i][j] = 0.f;

    for (int k0 = 0; k0 < RPS; k0 += TK) {
#pragma unroll
        for (int i = 0; i < (TK * 64) / 256; i++) {   // 10 elems/thread
            int idx = t + 256 * i;
            int k   = idx >> 6;
            int row = row0 + k0 + k;                   // always < NN
            float v = 0.f;
            if (e_ok) v = __expf(A[(size_t)row * NE + e_base + e_loc]);
            Ps[k][e_loc] = v;
            if (PASS == 1) cs += v;
            Xs[k][e_loc] = X[(size_t)row * DD + e_loc];  // e_loc doubles as d-index
        }
        __syncthreads();
#pragma unroll
        for (int k = 0; k < TK; k++) {
            float4 p4 = *(const float4*)&Ps[k][ty * 4];
            float4 x4 = *(const float4*)&Xs[k][tx * 4];
            float pv[4] = {p4.x, p4.y, p4.z, p4.w};
            float xv[4] = {x4.x, x4.y, x4.z, x4.w};
#pragma unroll
            for (int i = 0; i < 4; i++)
#pragma unroll
                for (int j = 0; j < 4; j++) a[i][j] = fmaf(pv[i], xv[j], a[i][j]);
        }
        __syncthreads();
    }
#pragma unroll
    for (int i = 0; i < 4; i++) {
        int ge = e_base + ty * 4 + i;
        if (ge < NE) {
#pragma unroll
            for (int j = 0; j < 4; j++)
                atomicAdd(&acc[(size_t)ge * DD + tx * 4 + j], a[i][j]);
        }
    }
    if (PASS == 1) {
        cred[t] = cs;
        __syncthreads();
        if (t < 64 && e_ok) {
            float tot = cred[t] + cred[t + 64] + cred[t + 128] + cred[t + 192];
            atomicAdd(&g_csum[e_base + t], tot);
        }
    }
}

// ---------------- finalize1: edge = relu(acc/csum); y = edge @ W3 ----------------
__global__ __launch_bounds__(256) void finalize1_kernel(const float* __restrict__ W3) {
    __shared__ __align__(16) float Es[64][64];
    __shared__ __align__(16) float Ws[64][64];
    const int t  = threadIdx.x;
    const int e0 = blockIdx.x * 64;
    const int tx = t & 15, ty = t >> 4;
#pragma unroll
    for (int i = 0; i < 16; i++) {
        int idx = t + 256 * i;
        int r = idx >> 6, c = idx & 63;
        int ge = e0 + r;
        float v = 0.f;
        if (ge < NE) v = fmaxf(g_acc[(size_t)ge * DD + c] / g_csum[ge], 0.f);
        Es[r][c] = v;
        Ws[r][c] = W3[idx];
    }
    __syncthreads();
    float a[4][4];
#pragma unroll
    for (int i = 0; i < 4; i++)
#pragma unroll
        for (int j = 0; j < 4; j++) a[i][j] = 0.f;
#pragma unroll
    for (int k = 0; k < 64; k++) {
        float ev[4];
#pragma unroll
        for (int i = 0; i < 4; i++) ev[i] = Es[ty * 4 + i][k];
        float4 w4 = *(const float4*)&Ws[k][tx * 4];
        float wv[4] = {w4.x, w4.y, w4.z, w4.w};
#pragma unroll
        for (int i = 0; i < 4; i++)
#pragma unroll
            for (int j = 0; j < 4; j++) a[i][j] = fmaf(ev[i], wv[j], a[i][j]);
    }
#pragma unroll
    for (int i = 0; i < 4; i++) {
        int ge = e0 + ty * 4 + i;
        if (ge < NE) {
#pragma unroll
            for (int j = 0; j < 4; j++) g_y[(size_t)ge * DD + tx * 4 + j] = a[i][j];
        }
    }
}

// ---------------- pass 2: node = relu( (sum_e exp(A[n,e]) y[e,:]) / rsum[n] ) ----
__global__ __launch_bounds__(256) void pass_n_kernel(const float* __restrict__ A) {
    __shared__ float Ps[TN][TK];               // exp tile, [row][k]
    __shared__ __align__(16) float Ys[TK][64];
    __shared__ float rowsum[TN];
    const int t  = threadIdx.x;
    const int n0 = blockIdx.x * TN;
    const int tx = t & 15, ty = t >> 4;        // ty in [0,16): 2 rows each
    float a[2][4];
#pragma unroll
    for (int i = 0; i < 2; i++)
#pragma unroll
        for (int j = 0; j < 4; j++) a[i][j] = 0.f;
    float rs = 0.f;

    for (int e0 = 0; e0 < NE; e0 += TK) {
#pragma unroll
        for (int i = 0; i < (TN * TK) / 256; i++) {   // 5 elems/thread
            int idx = t + 256 * i;
            int r = idx / TK;
            int k = idx - r * TK;
            int n = n0 + r;
            Ps[r][k] = (n < NN) ? __expf(A[(size_t)n * NE + e0 + k]) : 0.f;
        }
#pragma unroll
        for (int i = 0; i < (TK * 64) / 256; i++) {   // 10 elems/thread
            int idx = t + 256 * i;
            int k = idx >> 6, d = idx & 63;
            Ys[k][d] = g_y[(size_t)(e0 + k) * DD + d];
        }
        __syncthreads();
        if (t < TN) {                                  // row exp-sums (read-only on Ps)
            float s = 0.f;
#pragma unroll
            for (int k = 0; k < TK; k++) s += Ps[t][k];
            rs += s;
        }
#pragma unroll
        for (int k = 0; k < TK; k++) {
            float p0 = Ps[ty * 2 + 0][k];
            float p1 = Ps[ty * 2 + 1][k];
            float4 y4 = *(const float4*)&Ys[k][tx * 4];
            float yv[4] = {y4.x, y4.y, y4.z, y4.w};
#pragma unroll
            for (int j = 0; j < 4; j++) {
                a[0][j] = fmaf(p0, yv[j], a[0][j]);
                a[1][j] = fmaf(p1, yv[j], a[1][j]);
            }
        }
        __syncthreads();
    }
    if (t < TN) rowsum[t] = rs;
    __syncthreads();
#pragma unroll
    for (int i = 0; i < 2; i++) {
        int n = n0 + ty * 2 + i;
        if (n < NN) {
            float inv = 1.f / rowsum[ty * 2 + i];
#pragma unroll
            for (int j = 0; j < 4; j++)
                g_node[(size_t)n * DD + tx * 4 + j] = fmaxf(a[i][j] * inv, 0.f);
        }
    }
}

// ---------------- finalize3: out_edges = BN(relu(acc2/csum)) ----------------
__global__ void finalize3_kernel(const float* __restrict__ gamma,
                                 const float* __restrict__ beta,
                                 float* __restrict__ out_edges) {
    int idx = blockIdx.x * 256 + threadIdx.x;
    if (idx < NE * DD) {
        int e = idx >> 6, d = idx & 63;
        float v = fmaxf(g_acc2[idx] / g_csum[e], 0.f);
        float scale = gamma[d] * rsqrtf(1.f + 1e-5f);
        out_edges[idx] = v * scale + beta[d];
    }
}

// ---------------- fusion: fe' = s0*fe + s1*BN(node), attention over {fe, node} ---
__global__ __launch_bounds__(256) void fusion_kernel(const float* __restrict__ fe_old,
                                                     const float* __restrict__ gamma,
                                                     const float* __restrict__ beta,
                                                     const float* __restrict__ w1,
                                                     const float* __restrict__ b1,
                                                     const float* __restrict__ w2,
                                                     float* __restrict__ out_nodes) {
    __shared__ float w1s[64 * 64];
    __shared__ float b1s[64], w2s[64], gs[64], bs[64];
    const int t = threadIdx.x;
#pragma unroll
    for (int i = 0; i < 16; i++) w1s[t + 256 * i] = w1[t + 256 * i];
    if (t < 64) {
        b1s[t] = b1[t];
        w2s[t] = w2[t];
        gs[t]  = gamma[t] * rsqrtf(1.f + 1e-5f);
        bs[t]  = beta[t];
    }
    __syncthreads();
    const int warp = t >> 5, lane = t & 31;
    const int NPW = 4;
    const int nbase = blockIdx.x * (8 * NPW) + warp * NPW;
    for (int it = 0; it < NPW; it++) {
        int n = nbase + it;
        if (n >= NN) break;                      // warp-uniform
        size_t off = (size_t)n * DD;
        float f0 = fe_old[off + lane], f1 = fe_old[off + lane + 32];
        float nb0 = fmaf(g_node[off + lane],      gs[lane],      bs[lane]);
        float nb1 = fmaf(g_node[off + lane + 32], gs[lane + 32], bs[lane + 32]);
        float ha0 = b1s[lane], ha1 = b1s[lane + 32];
        float hb0 = ha0, hb1 = ha1;
#pragma unroll
        for (int k = 0; k < 64; k++) {
            float fk = __shfl_sync(0xffffffffu, (k < 32) ? f0 : f1, k & 31);
            float nk = __shfl_sync(0xffffffffu, (k < 32) ? nb0 : nb1, k & 31);
            float wa = w1s[k * 64 + lane];
            float wb = w1s[k * 64 + lane + 32];
            ha0 = fmaf(fk, wa, ha0); ha1 = fmaf(fk, wb, ha1);
            hb0 = fmaf(nk, wa, hb0); hb1 = fmaf(nk, wb, hb1);
        }
        ha0 = tanhf(ha0); ha1 = tanhf(ha1);
        hb0 = tanhf(hb0); hb1 = tanhf(hb1);
        float pa = ha0 * w2s[lane] + ha1 * w2s[lane + 32];
        float pb = hb0 * w2s[lane] + hb1 * w2s[lane + 32];
#pragma unroll
        for (int o = 16; o > 0; o >>= 1) {
            pa += __shfl_down_sync(0xffffffffu, pa, o);
            pb += __shfl_down_sync(0xffffffffu, pb, o);
        }
        pa = __shfl_sync(0xffffffffu, pa, 0);
        pb = __shfl_sync(0xffffffffu, pb, 0);
        float s0 = 1.f / (1.f + expf(pb - pa));   // softmax over {fe, node} (b2 cancels)
        out_nodes[off + lane]      = s0 * f0 + (1.f - s0) * nb0;
        out_nodes[off + lane + 32] = s0 * f1 + (1.f - s0) * nb1;
    }
}

// ---------------- launch ----------------
extern "C" void kernel_launch(void* const* d_in, const int* in_sizes, int n_in,
                              void* d_out, int out_size) {
    const float* fe    = (const float*)d_in[0];   // [N, D]
    const float* adj   = (const float*)d_in[1];   // [S, N, E]
    const float* W2    = (const float*)d_in[2];   // [D, D]
    const float* W3    = (const float*)d_in[3];   // [D, D]
    const float* gamma = (const float*)d_in[4];   // [D]
    const float* beta  = (const float*)d_in[5];   // [D]
    const float* fw1   = (const float*)d_in[6];   // [D, D]
    const float* fb1   = (const float*)d_in[7];   // [D]
    const float* fw2   = (const float*)d_in[8];   // [D, 1]
    // d_in[9] = fus_b2 (cancels in softmax), d_in[10] = root_idx (unused)
    float* out = (float*)d_out;

    const float* fe_cur = fe;
    for (int s = 0; s < NS; s++) {
        const float* A    = adj + (size_t)s * NN * NE;
        float* out_nodes  = out + (size_t)s * (NN + NE) * DD;
        float* out_edges  = out_nodes + (size_t)NN * DD;

        zero_scratch_kernel<<<(EPAD * DD) / 256, 256>>>();
        gemm_x_kernel<<<(NN + 63) / 64, 256>>>(fe_cur, W2);

        dim3 gbig(32, NSPLIT);
        pass_et_kernel<1><<<gbig, 256>>>(A);               // edge_pre + csum
        finalize1_kernel<<<32, 256>>>(W3);                 // y = relu(edge) @ W3
        pass_n_kernel<<<(NN + TN - 1) / TN, 256>>>(A);     // node (pre-BN)
        pass_et_kernel<3><<<gbig, 256>>>(A);               // edge2_pre
        finalize3_kernel<<<(NE * DD + 255) / 256, 256>>>(gamma, beta, out_edges);
        fusion_kernel<<<(NN + 31) / 32, 256>>>(fe_cur, gamma, beta, fw1, fb1, fw2, out_nodes);

        fe_cur = out_nodes;   // chained fe through the output buffer
    }
}

// round 5
// speedup vs baseline: 1.0329x; 1.0329x over previous
#include <cuda_runtime.h>
#include <math.h>

#define NN 20000
#define NE 2000
#define DD 64
#define NS 3
#define EPAD 2048

// pass_et: e-tile 256 x 8 blocks, 37 row-splits -> 296 blocks = 2/SM, one wave
#define ET_TK 25
#define ET_NSPLIT 37
// pass_n: n-tile 64, 128 threads, TK 40
#define PN_TK 40

typedef unsigned long long u64;

// ---------------- scratch (static device globals; no allocation) ----------------
__device__ float g_expA[NN * NE];   // exp(adj[s]) materialized once per subgraph
__device__ float g_x[NN * DD];      // fe @ W2
__device__ float g_y[EPAD * DD];    // relu(edge) @ W3
__device__ float g_node[NN * DD];   // pre-BN node
__device__ float g_acc[EPAD * DD];  // pass1 split-K accumulator
__device__ float g_acc2[EPAD * DD]; // pass3 split-K accumulator
__device__ float g_csum[EPAD];      // column exp-sums

// ---------------- f32x2 helpers ----------------
__device__ __forceinline__ u64 dup2(float x) {
    u64 r; asm("mov.b64 %0, {%1, %1};" : "=l"(r) : "f"(x)); return r;
}
__device__ __forceinline__ float2 unpk(u64 v) {
    float2 r; asm("mov.b64 {%0, %1}, %2;" : "=f"(r.x), "=f"(r.y) : "l"(v)); return r;
}
__device__ __forceinline__ void fma2(u64& d, u64 a, u64 b) {
    asm("fma.rn.f32x2 %0, %1, %2, %0;" : "+l"(d) : "l"(a), "l"(b));
}
__device__ __forceinline__ void red4(float* p, float a, float b, float c, float d) {
    asm volatile("red.global.add.v4.f32 [%0], {%1, %2, %3, %4};"
                 :: "l"(p), "f"(a), "f"(b), "f"(c), "f"(d) : "memory");
}

// ---------------- zero scratch (grid 512x256 == EPAD*DD exactly) ----------------
__global__ void zero_scratch_kernel() {
    int i = blockIdx.x * blockDim.x + threadIdx.x;
    g_acc[i]  = 0.f;
    g_acc2[i] = 0.f;
    if (i < EPAD) g_csum[i] = 0.f;
}

// ---------------- x = fe @ W2   [N,64]x[64,64] ----------------
__global__ __launch_bounds__(256) void gemm_x_kernel(const float* __restrict__ Fe,
                                                     const float* __restrict__ W2) {
    __shared__ __align__(16) float Fs[64][64];
    __shared__ __align__(16) float Ws[64][64];
    const int t  = threadIdx.x;
    const int n0 = blockIdx.x * 64;
    const int tx = t & 15, ty = t >> 4;
#pragma unroll
    for (int i = 0; i < 16; i++) {
        int idx = t + 256 * i;
        int r = idx >> 6, c = idx & 63;
        int n = n0 + r;
        Fs[r][c] = (n < NN) ? Fe[n * DD + c] : 0.f;
        Ws[r][c] = W2[idx];
    }
    __syncthreads();
    float a[4][4];
#pragma unroll
    for (int i = 0; i < 4; i++)
#pragma unroll
        for (int j = 0; j < 4; j++) a[i][j] = 0.f;
#pragma unroll
    for (int k = 0; k < 64; k++) {
        float fv[4];
#pragma unroll
        for (int i = 0; i < 4; i++) fv[i] = Fs[ty * 4 + i][k];
        float4 w4 = *(const float4*)&Ws[k][tx * 4];
        float wv[4] = {w4.x, w4.y, w4.z, w4.w};
#pragma unroll
        for (int i = 0; i < 4; i++)
#pragma unroll
            for (int j = 0; j < 4; j++) a[i][j] = fmaf(fv[i], wv[j], a[i][j]);
    }
#pragma unroll
    for (int i = 0; i < 4; i++) {
        int n = n0 + ty * 4 + i;
        if (n < NN) {
#pragma unroll
            for (int j = 0; j < 4; j++) g_x[n * DD + tx * 4 + j] = a[i][j];
        }
    }
}

// ---------------- pass 1 / pass 3: acc[e,d] += sum_n expA[n,e] * X[n,d] --------
// PASS==1: X=g_x, acc=g_acc; computes exp(A), writes g_expA, accumulates g_csum.
// PASS==3: X=g_node, acc=g_acc2; reads g_expA.
// Block: 256 threads, tile 256e x 64d, per-thread 8x8 via f32x2 (row-paired accs).
template <int PASS>
__global__ __launch_bounds__(256, 2) void pass_et_kernel(const float* __restrict__ A) {
    const float* __restrict__ X = (PASS == 1) ? g_x : g_node;
    float* __restrict__ acc = (PASS == 1) ? g_acc : g_acc2;
    __shared__ __align__(16) float Ps[ET_TK][256];
    __shared__ __align__(16) float Xs[ET_TK][64];
    const int t      = threadIdx.x;
    const int e_base = blockIdx.x * 256;
    const int split  = blockIdx.y;
    // 20000 = 20*541 + 17*540
    const int row0   = split * 540 + (split < 20 ? split : 20);
    const int nrows  = 540 + (split < 20 ? 1 : 0);
    const int tx8 = t & 7;      // d cols tx8*8 .. +7
    const int ty8 = t >> 3;     // e rows ty8*8 .. +7
    const int e_col  = e_base + t;
    const bool e_ok  = e_col < NE;

    u64 av[4][8];
#pragma unroll
    for (int r = 0; r < 4; r++)
#pragma unroll
        for (int c = 0; c < 8; c++) av[r][c] = 0ull;
    float cs = 0.f;

    for (int k0 = 0; k0 < nrows; k0 += ET_TK) {
        // load P tile: thread t owns e-column t, 25 rows
#pragma unroll
        for (int i = 0; i < ET_TK; i++) {
            float v = 0.f;
            int kk = k0 + i;
            if (kk < nrows && e_ok) {
                int row = row0 + kk;
                if (PASS == 1) {
                    v = __expf(A[row * NE + e_col]);
                    g_expA[row * NE + e_col] = v;
                    cs += v;
                } else {
                    v = g_expA[row * NE + e_col];
                }
            }
            Ps[i][t] = v;
        }
        // load X tile [25][64]
#pragma unroll
        for (int i = 0; i < 7; i++) {
            int idx = t + 256 * i;
            if (idx < ET_TK * 64) {
                int k = idx >> 6, d = idx & 63;
                float v = 0.f;
                if (k0 + k < nrows) v = X[(row0 + k0 + k) * DD + d];
                Xs[k][d] = v;
            }
        }
        __syncthreads();
#pragma unroll
        for (int k = 0; k < ET_TK; k++) {
            ulonglong2 pA = *(const ulonglong2*)&Ps[k][ty8 * 8];
            ulonglong2 pB = *(const ulonglong2*)&Ps[k][ty8 * 8 + 4];
            float4 xA = *(const float4*)&Xs[k][tx8 * 8];
            float4 xB = *(const float4*)&Xs[k][tx8 * 8 + 4];
            u64 xd[8];
            xd[0] = dup2(xA.x); xd[1] = dup2(xA.y); xd[2] = dup2(xA.z); xd[3] = dup2(xA.w);
            xd[4] = dup2(xB.x); xd[5] = dup2(xB.y); xd[6] = dup2(xB.z); xd[7] = dup2(xB.w);
            u64 pr[4] = {pA.x, pA.y, pB.x, pB.y};
#pragma unroll
            for (int r = 0; r < 4; r++)
#pragma unroll
                for (int c = 0; c < 8; c++) fma2(av[r][c], pr[r], xd[c]);
        }
        __syncthreads();
    }
    // epilogue: vectorized global reductions
#pragma unroll
    for (int r = 0; r < 4; r++) {
        float2 v[8];
#pragma unroll
        for (int c = 0; c < 8; c++) v[c] = unpk(av[r][c]);
        int e0r = e_base + ty8 * 8 + r * 2;
        if (e0r < NE) {
            red4(&acc[e0r * DD + tx8 * 8],     v[0].x, v[1].x, v[2].x, v[3].x);
            red4(&acc[e0r * DD + tx8 * 8 + 4], v[4].x, v[5].x, v[6].x, v[7].x);
        }
        if (e0r + 1 < NE) {
            red4(&acc[(e0r + 1) * DD + tx8 * 8],     v[0].y, v[1].y, v[2].y, v[3].y);
            red4(&acc[(e0r + 1) * DD + tx8 * 8 + 4], v[4].y, v[5].y, v[6].y, v[7].y);
        }
    }
    if (PASS == 1 && e_ok) atomicAdd(&g_csum[e_col], cs);
}

// ---------------- finalize1: edge = relu(acc/csum); y = edge @ W3 ----------------
__global__ __launch_bounds__(256) void finalize1_kernel(const float* __restrict__ W3) {
    __shared__ __align__(16) float Es[64][64];
    __shared__ __align__(16) float Ws[64][64];
    const int t  = threadIdx.x;
    const int e0 = blockIdx.x * 64;
    const int tx = t & 15, ty = t >> 4;
#pragma unroll
    for (int i = 0; i < 16; i++) {
        int idx = t + 256 * i;
        int r = idx >> 6, c = idx & 63;
        int ge = e0 + r;
        float v = 0.f;
        if (ge < NE) v = fmaxf(g_acc[ge * DD + c] / g_csum[ge], 0.f);
        Es[r][c] = v;
        Ws[r][c] = W3[idx];
    }
    __syncthreads();
    float a[4][4];
#pragma unroll
    for (int i = 0; i < 4; i++)
#pragma unroll
        for (int j = 0; j < 4; j++) a[i][j] = 0.f;
#pragma unroll
    for (int k = 0; k < 64; k++) {
        float ev[4];
#pragma unroll
        for (int i = 0; i < 4; i++) ev[i] = Es[ty * 4 + i][k];
        float4 w4 = *(const float4*)&Ws[k][tx * 4];
        float wv[4] = {w4.x, w4.y, w4.z, w4.w};
#pragma unroll
        for (int i = 0; i < 4; i++)
#pragma unroll
            for (int j = 0; j < 4; j++) a[i][j] = fmaf(ev[i], wv[j], a[i][j]);
    }
#pragma unroll
    for (int i = 0; i < 4; i++) {
        int ge = e0 + ty * 4 + i;
        if (ge < NE) {
#pragma unroll
            for (int j = 0; j < 4; j++) g_y[ge * DD + tx * 4 + j] = a[i][j];
        }
    }
}

// ---------------- pass 2: node = relu( (sum_e expA[n,e] y[e,:]) / rsum[n] ) ----
// Block: 128 threads, tile 64n x 64d, per-thread 4x8 via f32x2; rowsum folded
// into the FMA stream as fma2(rs, p, {1,1}); each thread normalizes locally.
__global__ __launch_bounds__(128, 4) void pass_n_kernel() {
    __shared__ __align__(16) float PsT[PN_TK][68];   // stride 68: 16B-aligned rows, conflict-light
    __shared__ __align__(16) float Ys[PN_TK][64];
    const int t   = threadIdx.x;
    const int n0  = blockIdx.x * 64;
    const int tx8 = t & 7;      // d cols tx8*8 .. +7
    const int tyr = t >> 3;     // n rows tyr*4 .. +3
    u64 av[2][8];
#pragma unroll
    for (int r = 0; r < 2; r++)
#pragma unroll
        for (int c = 0; c < 8; c++) av[r][c] = 0ull;
    u64 rs[2] = {0ull, 0ull};
    const u64 ONE2 = dup2(1.0f);

    for (int e0 = 0; e0 < NE; e0 += PN_TK) {
        // load 64x40 expA tile, transposed into PsT[k][n]
#pragma unroll
        for (int i = 0; i < 20; i++) {
            int idx = t + 128 * i;
            int nr = idx / PN_TK;
            int k  = idx - nr * PN_TK;
            int n  = n0 + nr;
            PsT[k][nr] = (n < NN) ? g_expA[n * NE + e0 + k] : 0.f;
        }
        // load Y tile [40][64]
#pragma unroll
        for (int i = 0; i < 20; i++) {
            int idx = t + 128 * i;
            int k = idx >> 6, d = idx & 63;
            Ys[k][d] = g_y[(e0 + k) * DD + d];
        }
        __syncthreads();
#pragma unroll
        for (int k = 0; k < PN_TK; k++) {
            ulonglong2 p2 = *(const ulonglong2*)&PsT[k][tyr * 4];
            float4 yA = *(const float4*)&Ys[k][tx8 * 8];
            float4 yB = *(const float4*)&Ys[k][tx8 * 8 + 4];
            u64 yd[8];
            yd[0] = dup2(yA.x); yd[1] = dup2(yA.y); yd[2] = dup2(yA.z); yd[3] = dup2(yA.w);
            yd[4] = dup2(yB.x); yd[5] = dup2(yB.y); yd[6] = dup2(yB.z); yd[7] = dup2(yB.w);
            u64 pr[2] = {p2.x, p2.y};
            fma2(rs[0], pr[0], ONE2);
            fma2(rs[1], pr[1], ONE2);
#pragma unroll
            for (int r = 0; r < 2; r++)
#pragma unroll
                for (int c = 0; c < 8; c++) fma2(av[r][c], pr[r], yd[c]);
        }
        __syncthreads();
    }
    float2 s01 = unpk(rs[0]), s23 = unpk(rs[1]);
    float ri[4] = {1.f / s01.x, 1.f / s01.y, 1.f / s23.x, 1.f / s23.y};
#pragma unroll
    for (int r = 0; r < 2; r++) {
        float2 v[8];
#pragma unroll
        for (int c = 0; c < 8; c++) v[c] = unpk(av[r][c]);
        int n_lo = n0 + tyr * 4 + r * 2;
        if (n_lo < NN) {
            float s = ri[r * 2];
            float4 o0 = {fmaxf(v[0].x, 0.f) * s, fmaxf(v[1].x, 0.f) * s,
                         fmaxf(v[2].x, 0.f) * s, fmaxf(v[3].x, 0.f) * s};
            float4 o1 = {fmaxf(v[4].x, 0.f) * s, fmaxf(v[5].x, 0.f) * s,
                         fmaxf(v[6].x, 0.f) * s, fmaxf(v[7].x, 0.f) * s};
            *(float4*)&g_node[n_lo * DD + tx8 * 8]     = o0;
            *(float4*)&g_node[n_lo * DD + tx8 * 8 + 4] = o1;
        }
        if (n_lo + 1 < NN) {
            float s = ri[r * 2 + 1];
            float4 o0 = {fmaxf(v[0].y, 0.f) * s, fmaxf(v[1].y, 0.f) * s,
                         fmaxf(v[2].y, 0.f) * s, fmaxf(v[3].y, 0.f) * s};
            float4 o1 = {fmaxf(v[4].y, 0.f) * s, fmaxf(v[5].y, 0.f) * s,
                         fmaxf(v[6].y, 0.f) * s, fmaxf(v[7].y, 0.f) * s};
            *(float4*)&g_node[(n_lo + 1) * DD + tx8 * 8]     = o0;
            *(float4*)&g_node[(n_lo + 1) * DD + tx8 * 8 + 4] = o1;
        }
    }
}

// ---------------- finalize3: out_edges = BN(relu(acc2/csum)) ----------------
__global__ void finalize3_kernel(const float* __restrict__ gamma,
                                 const float* __restrict__ beta,
                                 float* __restrict__ out_edges) {
    int idx = blockIdx.x * 256 + threadIdx.x;
    if (idx < NE * DD) {
        int e = idx >> 6, d = idx & 63;
        float v = fmaxf(g_acc2[idx] / g_csum[e], 0.f);
        float scale = gamma[d] * rsqrtf(1.f + 1e-5f);
        out_edges[idx] = v * scale + beta[d];
    }
}

// ---------------- fusion: fe' = s0*fe + s1*BN(node), attention over {fe, node} ---
__global__ __launch_bounds__(256) void fusion_kernel(const float* __restrict__ fe_old,
                                                     const float* __restrict__ gamma,
                                                     const float* __restrict__ beta,
                                                     const float* __restrict__ w1,
                                                     const float* __restrict__ b1,
                                                     const float* __restrict__ w2,
                                                     float* __restrict__ out_nodes) {
    __shared__ float w1s[64 * 64];
    __shared__ float b1s[64], w2s[64], gs[64], bs[64];
    const int t = threadIdx.x;
#pragma unroll
    for (int i = 0; i < 16; i++) w1s[t + 256 * i] = w1[t + 256 * i];
    if (t < 64) {
        b1s[t] = b1[t];
        w2s[t] = w2[t];
        gs[t]  = gamma[t] * rsqrtf(1.f + 1e-5f);
        bs[t]  = beta[t];
    }
    __syncthreads();
    const int warp = t >> 5, lane = t & 31;
    const int NPW = 4;
    const int nbase = blockIdx.x * (8 * NPW) + warp * NPW;
    for (int it = 0; it < NPW; it++) {
        int n = nbase + it;
        if (n >= NN) break;                      // warp-uniform
        int off = n * DD;
        float f0 = fe_old[off + lane], f1 = fe_old[off + lane + 32];
        float nb0 = fmaf(g_node[off + lane],      gs[lane],      bs[lane]);
        float nb1 = fmaf(g_node[off + lane + 32], gs[lane + 32], bs[lane + 32]);
        float ha0 = b1s[lane], ha1 = b1s[lane + 32];
        float hb0 = ha0, hb1 = ha1;
#pragma unroll
        for (int k = 0; k < 64; k++) {
            float fk = __shfl_sync(0xffffffffu, (k < 32) ? f0 : f1, k & 31);
            float nk = __shfl_sync(0xffffffffu, (k < 32) ? nb0 : nb1, k & 31);
            float wa = w1s[k * 64 + lane];
            float wb = w1s[k * 64 + lane + 32];
            ha0 = fmaf(fk, wa, ha0); ha1 = fmaf(fk, wb, ha1);
            hb0 = fmaf(nk, wa, hb0); hb1 = fmaf(nk, wb, hb1);
        }
        ha0 = tanhf(ha0); ha1 = tanhf(ha1);
        hb0 = tanhf(hb0); hb1 = tanhf(hb1);
        float pa = ha0 * w2s[lane] + ha1 * w2s[lane + 32];
        float pb = hb0 * w2s[lane] + hb1 * w2s[lane + 32];
#pragma unroll
        for (int o = 16; o > 0; o >>= 1) {
            pa += __shfl_down_sync(0xffffffffu, pa, o);
            pb += __shfl_down_sync(0xffffffffu, pb, o);
        }
        pa = __shfl_sync(0xffffffffu, pa, 0);
        pb = __shfl_sync(0xffffffffu, pb, 0);
        float s0 = 1.f / (1.f + expf(pb - pa));   // softmax over {fe, node} (b2 cancels)
        out_nodes[off + lane]      = s0 * f0 + (1.f - s0) * nb0;
        out_nodes[off + lane + 32] = s0 * f1 + (1.f - s0) * nb1;
    }
}

// ---------------- launch ----------------
extern "C" void kernel_launch(void* const* d_in, const int* in_sizes, int n_in,
                              void* d_out, int out_size) {
    const float* fe    = (const float*)d_in[0];   // [N, D]
    const float* adj   = (const float*)d_in[1];   // [S, N, E]
    const float* W2    = (const float*)d_in[2];   // [D, D]
    const float* W3    = (const float*)d_in[3];   // [D, D]
    const float* gamma = (const float*)d_in[4];   // [D]
    const float* beta  = (const float*)d_in[5];   // [D]
    const float* fw1   = (const float*)d_in[6];   // [D, D]
    const float* fb1   = (const float*)d_in[7];   // [D]
    const float* fw2   = (const float*)d_in[8];   // [D, 1]
    // d_in[9] = fus_b2 (cancels in softmax), d_in[10] = root_idx (unused)
    float* out = (float*)d_out;

    const float* fe_cur = fe;
    for (int s = 0; s < NS; s++) {
        const float* A   = adj + (size_t)s * NN * NE;
        float* out_nodes = out + (size_t)s * (NN + NE) * DD;
        float* out_edges = out_nodes + (size_t)NN * DD;

        zero_scratch_kernel<<<(EPAD * DD) / 256, 256>>>();
        gemm_x_kernel<<<(NN + 63) / 64, 256>>>(fe_cur, W2);

        dim3 g_et(8, ET_NSPLIT);
        pass_et_kernel<1><<<g_et, 256>>>(A);               // exp+csum+expA + edge_pre
        finalize1_kernel<<<32, 256>>>(W3);                 // y = relu(edge) @ W3
        pass_n_kernel<<<(NN + 63) / 64, 128>>>();          // node (pre-BN)
        pass_et_kernel<3><<<g_et, 256>>>(A);               // edge2_pre (reads expA)
        finalize3_kernel<<<(NE * DD + 255) / 256, 256>>>(gamma, beta, out_edges);
        fusion_kernel<<<(NN + 31) / 32, 256>>>(fe_cur, gamma, beta, fw1, fb1, fw2, out_nodes);

        fe_cur = out_nodes;   // chained fe through the output buffer
    }
}